// round 14
// baseline (speedup 1.0000x reference)
#include <cuda_runtime.h>

#define BATCH 2
#define NPTS 4096
#define NQ    16384
#define CHUNK 512
#define LDQ   36

typedef unsigned long long ULL;

// ---------------- scratch ----------------
__device__ float  g_feat[BATCH * NPTS * 448];  // [b][p][448] post-relu features
__device__ float  g_G[BATCH * NPTS * 256];     // [b][p][256]  feat @ W1[3:451]
__device__ float4 g_pts4[BATCH * NPTS];        // {-2x,-2y,-2z,|p|^2}
__device__ int    g_gmax[BATCH * 256];
__device__ float  g_c1[BATCH * 256];           // rb1 + W1[451:]@globalfeat
__device__ float  g_w1q[256 * 4];              // [oc]{w1x,w1y,w1z,0}
__device__ float  g_rG[112 * 1024];            // W1[3:451] packed [c/4][256 oc][4]
__device__ float  g_r2o[64 * 512];             // [k/4][128 oc][4]
__device__ float  g_r3o[32 * 256];             // [k/4][64 oc][4]

// ---------------- f32x2 helpers ----------------
__device__ __forceinline__ ULL pk2(float x) {
    ULL r; asm("mov.b64 %0, {%1, %1};" : "=l"(r) : "f"(x)); return r;
}
__device__ __forceinline__ void fma2(ULL& acc, ULL a, ULL b) {
    asm("fma.rn.f32x2 %0, %1, %2, %0;" : "+l"(acc) : "l"(a), "l"(b));
}
__device__ __forceinline__ void upk2(ULL v, float& lo, float& hi) {
    asm("mov.b64 {%0, %1}, %2;" : "=f"(lo), "=f"(hi) : "l"(v));
}

// ---------------- prep ----------------
__global__ void prep_kernel(const float* __restrict__ opts,
                            const float* __restrict__ r1, const float* __restrict__ r2,
                            const float* __restrict__ r3) {
    int stride = gridDim.x * blockDim.x;
    int tid = blockIdx.x * blockDim.x + threadIdx.x;
    if (tid < BATCH * 256) g_gmax[tid] = 0;
    for (int idx = tid; idx < BATCH * NPTS; idx += stride) {
        int b = idx >> 12, p = idx & (NPTS - 1);
        float x = opts[b * 3 * NPTS + p];
        float y = opts[b * 3 * NPTS + NPTS + p];
        float z = opts[b * 3 * NPTS + 2 * NPTS + p];
        g_pts4[idx] = make_float4(-2.f * x, -2.f * y, -2.f * z,
                                  x * x + y * y + z * z);
    }
    for (int idx = tid; idx < 448 * 256; idx += stride) {
        int c = idx >> 8, oc = idx & 255;
        g_rG[(c >> 2) * 1024 + oc * 4 + (c & 3)] = r1[oc * 707 + 3 + c];
    }
    for (int idx = tid; idx < 256 * 4; idx += stride) {
        int oc = idx >> 2, d = idx & 3;
        g_w1q[idx] = (d < 3) ? r1[oc * 707 + d] : 0.f;
    }
    for (int idx = tid; idx < 256 * 128; idx += stride) {
        int k = idx >> 7, oc = idx & 127;
        g_r2o[(k >> 2) * 512 + oc * 4 + (k & 3)] = r2[oc * 256 + k];
    }
    for (int idx = tid; idx < 128 * 64; idx += stride) {
        int k = idx >> 6, oc = idx & 63;
        g_r3o[(k >> 2) * 256 + oc * 4 + (k & 3)] = r3[oc * 128 + k];
    }
}

// ---------------- feature extractor ----------------
__global__ void feat_kernel(const float* __restrict__ opts,
                            const float* __restrict__ w1, const float* __restrict__ b1,
                            const float* __restrict__ w2, const float* __restrict__ b2,
                            const float* __restrict__ w3, const float* __restrict__ b3) {
    extern __shared__ float sm[];
    float* w2t = sm;             // 64*129
    float* w3t = w2t + 8256;     // 128*257
    float* f1s = w3t + 32896;    // 64*33
    float* f2s = f1s + 2112;     // 128*33
    float* pts = f2s + 4224;     // 96
    int t = threadIdx.x;
    int bb = blockIdx.x >> 7;
    int base = (blockIdx.x & 127) * 32;

    for (int i = t; i < 128 * 64; i += 256) { int oc = i >> 6, k = i & 63; w2t[k * 129 + oc] = w2[i]; }
    for (int i = t; i < 256 * 128; i += 256) { int oc = i >> 7, k = i & 127; w3t[k * 257 + oc] = w3[i]; }
    for (int i = t; i < 96; i += 256) {
        int d = i >> 5, j = i & 31;
        pts[i] = opts[bb * 3 * NPTS + d * NPTS + base + j];
    }
    __syncthreads();

    {   // 3 -> 64
        int oc = t & 63, jg = t >> 6;
        float wx = w1[oc * 3], wy = w1[oc * 3 + 1], wz = w1[oc * 3 + 2], bia = b1[oc];
        #pragma unroll
        for (int j = jg * 8; j < jg * 8 + 8; j++) {
            float v = fmaf(wx, pts[j], fmaf(wy, pts[32 + j], fmaf(wz, pts[64 + j], bia)));
            v = fmaxf(v, 0.f);
            f1s[oc * 33 + j] = v;
            g_feat[(bb * NPTS + base + j) * 448 + oc] = v;
        }
    }
    __syncthreads();

    {   // 64 -> 128
        int oc = t & 127, half = t >> 7;
        float acc[16];
        float bia = b2[oc];
        #pragma unroll
        for (int i = 0; i < 16; i++) acc[i] = bia;
        for (int k = 0; k < 64; k++) {
            float w = w2t[k * 129 + oc];
            const float* f = &f1s[k * 33 + half * 16];
            #pragma unroll
            for (int i = 0; i < 16; i++) acc[i] = fmaf(w, f[i], acc[i]);
        }
        for (int i = 0; i < 16; i++) {
            float v = fmaxf(acc[i], 0.f);
            int j = half * 16 + i;
            f2s[oc * 33 + j] = v;
            g_feat[(bb * NPTS + base + j) * 448 + 64 + oc] = v;
        }
    }
    __syncthreads();

    {   // 128 -> 256 + max
        int oc = t;
        float acc[32];
        float bia = b3[oc];
        #pragma unroll
        for (int i = 0; i < 32; i++) acc[i] = bia;
        for (int k = 0; k < 128; k++) {
            float w = w3t[k * 257 + oc];
            const float* f = &f2s[k * 33];
            #pragma unroll
            for (int j = 0; j < 32; j++) acc[j] = fmaf(w, f[j], acc[j]);
        }
        float mx = 0.f;
        for (int j = 0; j < 32; j++) {
            float v = fmaxf(acc[j], 0.f);
            g_feat[(bb * NPTS + base + j) * 448 + 192 + oc] = v;
            mx = fmaxf(mx, v);
        }
        atomicMax(&g_gmax[bb * 256 + oc], __float_as_int(mx));
    }
}

// ---------------- fold global feats into r1 bias ----------------
__global__ void c1_kernel(const float* __restrict__ r1, const float* __restrict__ rb1) {
    __shared__ float fms[256];
    int t = threadIdx.x;
    int bb = blockIdx.x >> 3;
    int ocbase = (blockIdx.x & 7) * 32;
    fms[t] = __int_as_float(g_gmax[bb * 256 + t]);
    __syncthreads();
    int oc = ocbase + (t >> 3);
    int seg = t & 7;
    const float* row = r1 + oc * 707 + 451 + seg * 32;
    float s = 0.f;
    #pragma unroll
    for (int i = 0; i < 32; i++) s = fmaf(row[i], fms[seg * 32 + i], s);
    s += __shfl_xor_sync(0xffffffffu, s, 1);
    s += __shfl_xor_sync(0xffffffffu, s, 2);
    s += __shfl_xor_sync(0xffffffffu, s, 4);
    if (seg == 0) g_c1[bb * 256 + oc] = s + rb1[oc];
}

// ---------------- G = feat @ W1[3:451]: 32 points x 128 ocs per block ----------------
// grid = BATCH * 128 pt-tiles * 2 oc-halves = 512; smem = 448*36*4 = 64512 B
__global__ void __launch_bounds__(256) gfeat_kernel() {
    extern __shared__ float fs[];   // [448][36]
    int t = threadIdx.x;
    int bb   = blockIdx.x >> 8;           // 256 blocks per batch
    int tile = (blockIdx.x >> 1) & 127;   // 128 point-tiles of 32
    int och  = blockIdx.x & 1;            // oc half: [och*128, och*128+128)
    int base = tile * 32;

    for (int idx = t; idx < 32 * 448; idx += 256) {
        int p = idx / 448, c = idx - p * 448;
        fs[c * LDQ + p] = g_feat[(size_t)(bb * NPTS + base + p) * 448 + c];
    }
    __syncthreads();

    int ocb = och * 128 + (t & 63);
    int p2 = (t >> 6) * 8;   // 8 points = 4 f32x2 pairs
    ULL acc[2][4];
    #pragma unroll
    for (int j = 0; j < 2; j++)
        #pragma unroll
        for (int i = 0; i < 4; i++) acc[j][i] = 0ULL;

    const float4* wb = (const float4*)g_rG;
    float4 w0 = wb[ocb], w1 = wb[ocb + 64];
    for (int cg = 0; cg < 112; cg++) {
        int cn = (cg < 111) ? cg + 1 : cg;
        float4 n0 = wb[cn * 256 + ocb];
        float4 n1 = wb[cn * 256 + ocb + 64];
        #pragma unroll
        for (int cc = 0; cc < 4; cc++) {
            const float* arow = fs + (cg * 4 + cc) * LDQ + p2;
            ulonglong2 aA = *(const ulonglong2*)(arow);
            ulonglong2 aB = *(const ulonglong2*)(arow + 4);
            float s0 = cc == 0 ? w0.x : cc == 1 ? w0.y : cc == 2 ? w0.z : w0.w;
            float s1 = cc == 0 ? w1.x : cc == 1 ? w1.y : cc == 2 ? w1.z : w1.w;
            ULL v0 = pk2(s0), v1 = pk2(s1);
            fma2(acc[0][0], v0, aA.x); fma2(acc[0][1], v0, aA.y);
            fma2(acc[0][2], v0, aB.x); fma2(acc[0][3], v0, aB.y);
            fma2(acc[1][0], v1, aA.x); fma2(acc[1][1], v1, aA.y);
            fma2(acc[1][2], v1, aB.x); fma2(acc[1][3], v1, aB.y);
        }
        w0 = n0; w1 = n1;
    }

    #pragma unroll
    for (int j = 0; j < 2; j++) {
        int oc = ocb + 64 * j;
        #pragma unroll
        for (int i = 0; i < 4; i++) {
            float lo, hi; upk2(acc[j][i], lo, hi);
            g_G[(size_t)(bb * NPTS + base + p2 + 2 * i)     * 256 + oc] = lo;
            g_G[(size_t)(bb * NPTS + base + p2 + 2 * i + 1) * 256 + oc] = hi;
        }
    }
}

// ---------------- warp top-3 merge returning dists ----------------
__device__ __forceinline__ void merge3d(float b0, float b1, float b2,
                                        int i0, int i1, int i2, int lane,
                                        int sel[3], float seld[3]) {
    int j = 0;
    #pragma unroll
    for (int s = 0; s < 3; s++) {
        float cv = (j == 0) ? b0 : ((j == 1) ? b1 : ((j == 2) ? b2 : 3.4e38f));
        int   ci = (j == 0) ? i0 : ((j == 1) ? i1 : i2);
        float rv = cv; int rl = lane;
        #pragma unroll
        for (int off = 16; off; off >>= 1) {
            float ov = __shfl_down_sync(0xffffffffu, rv, off);
            int   ol = __shfl_down_sync(0xffffffffu, rl, off);
            if (ov < rv) { rv = ov; rl = ol; }
        }
        int wl = __shfl_sync(0xffffffffu, rl, 0);
        seld[s] = __shfl_sync(0xffffffffu, rv, 0);
        sel[s]  = __shfl_sync(0xffffffffu, ci, wl);
        if (lane == wl) j++;
    }
}

// ---------------- fused KNN(3) + h1 build + stages 2-4 ----------------
// smem (floats): h1s[0,9216) h2s[9216,13824); overlays in h2s region pre-stage2:
//   c4 (float4[512]) [9216,11264), w1qs [11264,12288), c1s [12288,12544)
//   h3s overlays h1s after stage2. total 13824 floats = 55296 B -> 4 CTAs/SM
__global__ void __launch_bounds__(256, 4) knnreg_kernel(
        const float* __restrict__ qpts,
        const float* __restrict__ rb2, const float* __restrict__ rb3,
        const float* __restrict__ r4, const float* __restrict__ rb4,
        float* __restrict__ out) {
    extern __shared__ float sm[];
    float*  h1s  = sm;
    float*  h2s  = sm + 9216;
    float*  h3s  = sm;
    float4* c4   = (float4*)(sm + 9216);
    float*  w1qs = sm + 11264;
    float*  c1s  = sm + 12288;
    int t = threadIdx.x;
    int bb = blockIdx.x >> 9, tile = blockIdx.x & 511;
    int qbase = tile * 32;
    int warp = t >> 5, lane = t & 31;

    for (int i = t; i < 1024; i += 256) w1qs[i] = g_w1q[i];
    if (t < 256) c1s[t] = g_c1[bb * 256 + t];

    int q0 = qbase + warp * 4;
    float qx[4], qy[4], qz[4];
    #pragma unroll
    for (int r = 0; r < 4; r++) {
        qx[r] = qpts[bb * 3 * NQ + q0 + r];
        qy[r] = qpts[bb * 3 * NQ + NQ + q0 + r];
        qz[r] = qpts[bb * 3 * NQ + 2 * NQ + q0 + r];
    }

    float bd[4][3];
    int   bi[4][3];
    #pragma unroll
    for (int r = 0; r < 4; r++)
        #pragma unroll
        for (int s = 0; s < 3; s++) { bd[r][s] = 3.4e38f; bi[r][s] = 0; }

    const float4* pbase = g_pts4 + bb * NPTS;
    for (int ch = 0; ch < NPTS / CHUNK; ch++) {
        __syncthreads();
        for (int i = t; i < CHUNK; i += 256) c4[i] = pbase[ch * CHUNK + i];
        __syncthreads();
        int gb = ch * CHUNK;
        for (int p = lane; p < CHUNK; p += 32) {
            float4 P = c4[p];
            #pragma unroll
            for (int r = 0; r < 4; r++) {
                // dd = |p|^2 - 2 q.p  (ordering-equivalent to |p-q|^2)
                float dd = fmaf(qx[r], P.x, fmaf(qy[r], P.y, fmaf(qz[r], P.z, P.w)));
                if (dd < bd[r][2]) {
                    if (dd < bd[r][1]) {
                        bd[r][2] = bd[r][1]; bi[r][2] = bi[r][1];
                        if (dd < bd[r][0]) { bd[r][1] = bd[r][0]; bi[r][1] = bi[r][0]; bd[r][0] = dd; bi[r][0] = gb + p; }
                        else               { bd[r][1] = dd; bi[r][1] = gb + p; }
                    } else { bd[r][2] = dd; bi[r][2] = gb + p; }
                }
            }
        }
    }
    __syncthreads();

    // ---- per query: weights + gather G rows -> h1 ----
    #pragma unroll
    for (int r = 0; r < 4; r++) {
        int sel[3]; float seld[3];
        merge3d(bd[r][0], bd[r][1], bd[r][2], bi[r][0], bi[r][1], bi[r][2], lane, sel, seld);
        int ql = warp * 4 + r;

        float q2r = fmaf(qx[r], qx[r], fmaf(qy[r], qy[r], qz[r] * qz[r]));
        float wk0 = 1.f / (sqrtf(fmaxf(seld[0] + q2r, 0.f)) + 1e-8f);
        float wk1 = 1.f / (sqrtf(fmaxf(seld[1] + q2r, 0.f)) + 1e-8f);
        float wk2 = 1.f / (sqrtf(fmaxf(seld[2] + q2r, 0.f)) + 1e-8f);
        float inv = 1.f / (wk0 + wk1 + wk2);
        wk0 *= inv; wk1 *= inv; wk2 *= inv;

        const float4* G0 = (const float4*)(g_G + (size_t)(bb * NPTS + sel[0]) * 256);
        const float4* G1 = (const float4*)(g_G + (size_t)(bb * NPTS + sel[1]) * 256);
        const float4* G2 = (const float4*)(g_G + (size_t)(bb * NPTS + sel[2]) * 256);
        const float4* WQ = (const float4*)w1qs;
        #pragma unroll
        for (int h = 0; h < 2; h++) {
            int f4 = lane * 2 + h;
            float4 a = G0[f4], b = G1[f4], c = G2[f4];
            #pragma unroll
            for (int e = 0; e < 4; e++) {
                int oc = f4 * 4 + e;
                float4 w = WQ[oc];
                float ga  = e == 0 ? a.x : e == 1 ? a.y : e == 2 ? a.z : a.w;
                float gb2 = e == 0 ? b.x : e == 1 ? b.y : e == 2 ? b.z : b.w;
                float gc  = e == 0 ? c.x : e == 1 ? c.y : e == 2 ? c.z : c.w;
                float v = c1s[oc];
                v = fmaf(qx[r], w.x, v);
                v = fmaf(qy[r], w.y, v);
                v = fmaf(qz[r], w.z, v);
                v = fmaf(wk0, ga, v);
                v = fmaf(wk1, gb2, v);
                v = fmaf(wk2, gc, v);
                h1s[oc * LDQ + ql] = fmaxf(v, 0.f);
            }
        }
    }
    __syncthreads();

    int ocb = t & 63;
    int q2 = (t >> 6) * 8;

    // ---- stage 2: 256 -> 128 ----
    {
        ULL acc[2][4];
        #pragma unroll
        for (int j = 0; j < 2; j++) {
            ULL c = pk2(rb2[ocb + 64 * j]);
            #pragma unroll
            for (int i = 0; i < 4; i++) acc[j][i] = c;
        }
        const float4* wb = (const float4*)g_r2o;
        float4 w0 = wb[ocb], w1 = wb[ocb + 64];
        for (int kg = 0; kg < 64; kg++) {
            int kn = (kg < 63) ? kg + 1 : kg;
            float4 n0 = wb[kn * 128 + ocb];
            float4 n1 = wb[kn * 128 + ocb + 64];
            #pragma unroll
            for (int kk = 0; kk < 4; kk++) {
                const float* arow = h1s + (kg * 4 + kk) * LDQ + q2;
                ulonglong2 aA = *(const ulonglong2*)(arow);
                ulonglong2 aB = *(const ulonglong2*)(arow + 4);
                float s0 = kk == 0 ? w0.x : kk == 1 ? w0.y : kk == 2 ? w0.z : w0.w;
                float s1 = kk == 0 ? w1.x : kk == 1 ? w1.y : kk == 2 ? w1.z : w1.w;
                ULL v0 = pk2(s0), v1 = pk2(s1);
                fma2(acc[0][0], v0, aA.x); fma2(acc[0][1], v0, aA.y);
                fma2(acc[0][2], v0, aB.x); fma2(acc[0][3], v0, aB.y);
                fma2(acc[1][0], v1, aA.x); fma2(acc[1][1], v1, aA.y);
                fma2(acc[1][2], v1, aB.x); fma2(acc[1][3], v1, aB.y);
            }
            w0 = n0; w1 = n1;
        }
        __syncthreads();
        #pragma unroll
        for (int j = 0; j < 2; j++) {
            float* hrow = h2s + (ocb + 64 * j) * LDQ + q2;
            #pragma unroll
            for (int i = 0; i < 4; i++) {
                float lo, hi; upk2(acc[j][i], lo, hi);
                hrow[2 * i]     = fmaxf(lo, 0.f);
                hrow[2 * i + 1] = fmaxf(hi, 0.f);
            }
        }
    }
    __syncthreads();

    // ---- stage 3: 128 -> 64 ----
    {
        ULL acc[4];
        ULL c = pk2(rb3[ocb]);
        #pragma unroll
        for (int i = 0; i < 4; i++) acc[i] = c;
        const float4* wb = (const float4*)g_r3o;
        for (int kg = 0; kg < 32; kg++) {
            float4 w = wb[kg * 64 + ocb];
            #pragma unroll
            for (int kk = 0; kk < 4; kk++) {
                const float* arow = h2s + (kg * 4 + kk) * LDQ + q2;
                ulonglong2 aA = *(const ulonglong2*)(arow);
                ulonglong2 aB = *(const ulonglong2*)(arow + 4);
                float ws = kk == 0 ? w.x : kk == 1 ? w.y : kk == 2 ? w.z : w.w;
                ULL wv = pk2(ws);
                fma2(acc[0], wv, aA.x);
                fma2(acc[1], wv, aA.y);
                fma2(acc[2], wv, aB.x);
                fma2(acc[3], wv, aB.y);
            }
        }
        __syncthreads();
        float* hrow = h3s + ocb * LDQ + q2;
        #pragma unroll
        for (int i = 0; i < 4; i++) {
            float lo, hi; upk2(acc[i], lo, hi);
            hrow[2 * i]     = fmaxf(lo, 0.f);
            hrow[2 * i + 1] = fmaxf(hi, 0.f);
        }
    }
    __syncthreads();

    // ---- stage 4: 64 -> 1 ----
    {
        int w4 = t >> 5, l4 = t & 31;
        int qloc = w4 * 4 + (l4 >> 3);
        int c0 = l4 & 7;
        float p = 0.f;
        #pragma unroll
        for (int jj = 0; jj < 8; jj++) {
            int c = c0 + jj * 8;
            p = fmaf(r4[c], h3s[c * LDQ + qloc], p);
        }
        p += __shfl_xor_sync(0xffffffffu, p, 1);
        p += __shfl_xor_sync(0xffffffffu, p, 2);
        p += __shfl_xor_sync(0xffffffffu, p, 4);
        if ((l4 & 7) == 0) out[bb * NQ + qbase + qloc] = p + rb4[0];
    }
}

// ---------------- launch ----------------
extern "C" void kernel_launch(void* const* d_in, const int* in_sizes, int n_in,
                              void* d_out, int out_size) {
    const float* opts = (const float*)d_in[0];
    const float* qpts = (const float*)d_in[1];
    const float* w1 = (const float*)d_in[2];
    const float* b1 = (const float*)d_in[3];
    const float* w2 = (const float*)d_in[4];
    const float* b2 = (const float*)d_in[5];
    const float* w3 = (const float*)d_in[6];
    const float* b3 = (const float*)d_in[7];
    const float* r1 = (const float*)d_in[8];
    const float* rb1 = (const float*)d_in[9];
    const float* r2 = (const float*)d_in[10];
    const float* rb2 = (const float*)d_in[11];
    const float* r3 = (const float*)d_in[12];
    const float* rb3 = (const float*)d_in[13];
    const float* r4 = (const float*)d_in[14];
    const float* rb4 = (const float*)d_in[15];
    float* out = (float*)d_out;

    cudaFuncSetAttribute(feat_kernel, cudaFuncAttributeMaxDynamicSharedMemorySize, 190336);
    cudaFuncSetAttribute(gfeat_kernel, cudaFuncAttributeMaxDynamicSharedMemorySize, 64512);
    cudaFuncSetAttribute(knnreg_kernel, cudaFuncAttributeMaxDynamicSharedMemorySize, 55296);

    prep_kernel<<<64, 256>>>(opts, r1, r2, r3);
    feat_kernel<<<BATCH * (NPTS / 32), 256, 190336>>>(opts, w1, b1, w2, b2, w3, b3);
    c1_kernel<<<BATCH * 8, 256>>>(r1, rb1);
    gfeat_kernel<<<BATCH * 256, 256, 64512>>>();
    knnreg_kernel<<<BATCH * (NQ / 32), 256, 55296>>>(qpts, rb2, rb3, r4, rb4, out);
}

// round 15
// speedup vs baseline: 1.1523x; 1.1523x over previous
#include <cuda_runtime.h>

#define BATCH 2
#define NPTS 4096
#define NQ    16384
#define CHUNK 512
#define LDQ   36

typedef unsigned long long ULL;

// ---------------- scratch ----------------
__device__ float  g_feat[BATCH * NPTS * 448];  // [b][p][448] post-relu features
__device__ float  g_G[BATCH * NPTS * 256];     // [b][p][256]  feat @ W1[3:451]
__device__ float4 g_pts4[BATCH * NPTS];        // {-2x,-2y,-2z,|p|^2}
__device__ int    g_gmax[BATCH * 256];
__device__ float  g_c1[BATCH * 256];           // rb1 + W1[451:]@globalfeat
__device__ float  g_w1q[256 * 4];              // [oc]{w1x,w1y,w1z,0}
__device__ float  g_rG[112 * 1024];            // W1[3:451] packed [c/4][256 oc][4]
__device__ float  g_r2o[64 * 512];             // [k/4][128 oc][4]
__device__ float  g_r3o[32 * 256];             // [k/4][64 oc][4]

// ---------------- f32x2 helpers ----------------
__device__ __forceinline__ ULL pk2(float x) {
    ULL r; asm("mov.b64 %0, {%1, %1};" : "=l"(r) : "f"(x)); return r;
}
__device__ __forceinline__ void fma2(ULL& acc, ULL a, ULL b) {
    asm("fma.rn.f32x2 %0, %1, %2, %0;" : "+l"(acc) : "l"(a), "l"(b));
}
__device__ __forceinline__ void upk2(ULL v, float& lo, float& hi) {
    asm("mov.b64 {%0, %1}, %2;" : "=f"(lo), "=f"(hi) : "l"(v));
}

// ---------------- prep ----------------
__global__ void prep_kernel(const float* __restrict__ opts,
                            const float* __restrict__ r1, const float* __restrict__ r2,
                            const float* __restrict__ r3) {
    int stride = gridDim.x * blockDim.x;
    int tid = blockIdx.x * blockDim.x + threadIdx.x;
    if (tid < BATCH * 256) g_gmax[tid] = 0;
    for (int idx = tid; idx < BATCH * NPTS; idx += stride) {
        int b = idx >> 12, p = idx & (NPTS - 1);
        float x = opts[b * 3 * NPTS + p];
        float y = opts[b * 3 * NPTS + NPTS + p];
        float z = opts[b * 3 * NPTS + 2 * NPTS + p];
        g_pts4[idx] = make_float4(-2.f * x, -2.f * y, -2.f * z,
                                  x * x + y * y + z * z);
    }
    for (int idx = tid; idx < 448 * 256; idx += stride) {
        int c = idx >> 8, oc = idx & 255;
        g_rG[(c >> 2) * 1024 + oc * 4 + (c & 3)] = r1[oc * 707 + 3 + c];
    }
    for (int idx = tid; idx < 256 * 4; idx += stride) {
        int oc = idx >> 2, d = idx & 3;
        g_w1q[idx] = (d < 3) ? r1[oc * 707 + d] : 0.f;
    }
    for (int idx = tid; idx < 256 * 128; idx += stride) {
        int k = idx >> 7, oc = idx & 127;
        g_r2o[(k >> 2) * 512 + oc * 4 + (k & 3)] = r2[oc * 256 + k];
    }
    for (int idx = tid; idx < 128 * 64; idx += stride) {
        int k = idx >> 6, oc = idx & 63;
        g_r3o[(k >> 2) * 256 + oc * 4 + (k & 3)] = r3[oc * 128 + k];
    }
}

// ---------------- feature extractor (stages 2-3 in FFMA2) ----------------
// smem floats: w2t 8256 | w3t 32896 | f1s 64*34=2176 | f2s 128*34=4352 | pts 96
__global__ void feat_kernel(const float* __restrict__ opts,
                            const float* __restrict__ w1, const float* __restrict__ b1,
                            const float* __restrict__ w2, const float* __restrict__ b2,
                            const float* __restrict__ w3, const float* __restrict__ b3) {
    extern __shared__ float sm[];
    float* w2t = sm;
    float* w3t = w2t + 8256;
    float* f1s = w3t + 32896;
    float* f2s = f1s + 2176;
    float* pts = f2s + 4352;
    int t = threadIdx.x;
    int bb = blockIdx.x >> 7;
    int base = (blockIdx.x & 127) * 32;

    for (int i = t; i < 128 * 64; i += 256) { int oc = i >> 6, k = i & 63; w2t[k * 129 + oc] = w2[i]; }
    for (int i = t; i < 256 * 128; i += 256) { int oc = i >> 7, k = i & 127; w3t[k * 257 + oc] = w3[i]; }
    for (int i = t; i < 96; i += 256) {
        int d = i >> 5, j = i & 31;
        pts[i] = opts[bb * 3 * NPTS + d * NPTS + base + j];
    }
    __syncthreads();

    {   // 3 -> 64
        int oc = t & 63, jg = t >> 6;
        float wx = w1[oc * 3], wy = w1[oc * 3 + 1], wz = w1[oc * 3 + 2], bia = b1[oc];
        #pragma unroll
        for (int j = jg * 8; j < jg * 8 + 8; j++) {
            float v = fmaf(wx, pts[j], fmaf(wy, pts[32 + j], fmaf(wz, pts[64 + j], bia)));
            v = fmaxf(v, 0.f);
            f1s[oc * 34 + j] = v;
            g_feat[(bb * NPTS + base + j) * 448 + oc] = v;
        }
    }
    __syncthreads();

    {   // 64 -> 128, FFMA2 over point pairs
        int oc = t & 127, half = t >> 7;
        ULL acc[8];
        ULL bia = pk2(b2[oc]);
        #pragma unroll
        for (int i = 0; i < 8; i++) acc[i] = bia;
        for (int k = 0; k < 64; k++) {
            ULL wv = pk2(w2t[k * 129 + oc]);
            const ULL* f = (const ULL*)(f1s + k * 34 + half * 16);
            #pragma unroll
            for (int i = 0; i < 8; i++) fma2(acc[i], wv, f[i]);
        }
        #pragma unroll
        for (int i = 0; i < 8; i++) {
            float lo, hi; upk2(acc[i], lo, hi);
            int j = half * 16 + 2 * i;
            lo = fmaxf(lo, 0.f); hi = fmaxf(hi, 0.f);
            f2s[oc * 34 + j] = lo;
            f2s[oc * 34 + j + 1] = hi;
            g_feat[(bb * NPTS + base + j)     * 448 + 64 + oc] = lo;
            g_feat[(bb * NPTS + base + j + 1) * 448 + 64 + oc] = hi;
        }
    }
    __syncthreads();

    {   // 128 -> 256 + max, FFMA2 over point pairs
        int oc = t;
        ULL acc[16];
        ULL bia = pk2(b3[oc]);
        #pragma unroll
        for (int i = 0; i < 16; i++) acc[i] = bia;
        for (int k = 0; k < 128; k++) {
            ULL wv = pk2(w3t[k * 257 + oc]);
            const ULL* f = (const ULL*)(f2s + k * 34);
            #pragma unroll
            for (int i = 0; i < 16; i++) fma2(acc[i], wv, f[i]);
        }
        float mx = 0.f;
        #pragma unroll
        for (int i = 0; i < 16; i++) {
            float lo, hi; upk2(acc[i], lo, hi);
            lo = fmaxf(lo, 0.f); hi = fmaxf(hi, 0.f);
            g_feat[(bb * NPTS + base + 2 * i)     * 448 + 192 + oc] = lo;
            g_feat[(bb * NPTS + base + 2 * i + 1) * 448 + 192 + oc] = hi;
            mx = fmaxf(mx, fmaxf(lo, hi));
        }
        atomicMax(&g_gmax[bb * 256 + oc], __float_as_int(mx));
    }
}

// ---------------- fold global feats into r1 bias ----------------
__global__ void c1_kernel(const float* __restrict__ r1, const float* __restrict__ rb1) {
    __shared__ float fms[256];
    int t = threadIdx.x;
    int bb = blockIdx.x >> 3;
    int ocbase = (blockIdx.x & 7) * 32;
    fms[t] = __int_as_float(g_gmax[bb * 256 + t]);
    __syncthreads();
    int oc = ocbase + (t >> 3);
    int seg = t & 7;
    const float* row = r1 + oc * 707 + 451 + seg * 32;
    float s = 0.f;
    #pragma unroll
    for (int i = 0; i < 32; i++) s = fmaf(row[i], fms[seg * 32 + i], s);
    s += __shfl_xor_sync(0xffffffffu, s, 1);
    s += __shfl_xor_sync(0xffffffffu, s, 2);
    s += __shfl_xor_sync(0xffffffffu, s, 4);
    if (seg == 0) g_c1[bb * 256 + oc] = s + rb1[oc];
}

// ---------------- G = feat @ W1[3:451]: 32 points x 256 ocs (R8 config) ----------------
// grid = BATCH*128, smem = 448*36*4 = 64512 B
__global__ void __launch_bounds__(256) gfeat_kernel() {
    extern __shared__ float fs[];   // [448][36]
    int t = threadIdx.x;
    int bb = blockIdx.x >> 7;
    int base = (blockIdx.x & 127) * 32;

    for (int idx = t; idx < 32 * 448; idx += 256) {
        int p = idx / 448, c = idx - p * 448;
        fs[c * LDQ + p] = g_feat[(size_t)(bb * NPTS + base + p) * 448 + c];
    }
    __syncthreads();

    int ocb = t & 63;
    int p2 = (t >> 6) * 8;
    ULL acc[4][4];
    #pragma unroll
    for (int j = 0; j < 4; j++)
        #pragma unroll
        for (int i = 0; i < 4; i++) acc[j][i] = 0ULL;

    const float4* wb = (const float4*)g_rG;
    float4 w0 = wb[ocb], w1 = wb[ocb + 64], w2 = wb[ocb + 128], w3 = wb[ocb + 192];
    for (int cg = 0; cg < 112; cg++) {
        int cn = (cg < 111) ? cg + 1 : cg;
        float4 n0 = wb[cn * 256 + ocb];
        float4 n1 = wb[cn * 256 + ocb + 64];
        float4 n2 = wb[cn * 256 + ocb + 128];
        float4 n3 = wb[cn * 256 + ocb + 192];
        #pragma unroll
        for (int cc = 0; cc < 4; cc++) {
            const float* arow = fs + (cg * 4 + cc) * LDQ + p2;
            ulonglong2 aA = *(const ulonglong2*)(arow);
            ulonglong2 aB = *(const ulonglong2*)(arow + 4);
            float s0 = cc == 0 ? w0.x : cc == 1 ? w0.y : cc == 2 ? w0.z : w0.w;
            float s1 = cc == 0 ? w1.x : cc == 1 ? w1.y : cc == 2 ? w1.z : w1.w;
            float s2 = cc == 0 ? w2.x : cc == 1 ? w2.y : cc == 2 ? w2.z : w2.w;
            float s3 = cc == 0 ? w3.x : cc == 1 ? w3.y : cc == 2 ? w3.z : w3.w;
            ULL v0 = pk2(s0), v1 = pk2(s1), v2 = pk2(s2), v3 = pk2(s3);
            fma2(acc[0][0], v0, aA.x); fma2(acc[0][1], v0, aA.y);
            fma2(acc[0][2], v0, aB.x); fma2(acc[0][3], v0, aB.y);
            fma2(acc[1][0], v1, aA.x); fma2(acc[1][1], v1, aA.y);
            fma2(acc[1][2], v1, aB.x); fma2(acc[1][3], v1, aB.y);
            fma2(acc[2][0], v2, aA.x); fma2(acc[2][1], v2, aA.y);
            fma2(acc[2][2], v2, aB.x); fma2(acc[2][3], v2, aB.y);
            fma2(acc[3][0], v3, aA.x); fma2(acc[3][1], v3, aA.y);
            fma2(acc[3][2], v3, aB.x); fma2(acc[3][3], v3, aB.y);
        }
        w0 = n0; w1 = n1; w2 = n2; w3 = n3;
    }

    #pragma unroll
    for (int j = 0; j < 4; j++) {
        int oc = ocb + 64 * j;
        #pragma unroll
        for (int i = 0; i < 4; i++) {
            float lo, hi; upk2(acc[j][i], lo, hi);
            g_G[(size_t)(bb * NPTS + base + p2 + 2 * i)     * 256 + oc] = lo;
            g_G[(size_t)(bb * NPTS + base + p2 + 2 * i + 1) * 256 + oc] = hi;
        }
    }
}

// ---------------- warp top-3 merge returning dists ----------------
__device__ __forceinline__ void merge3d(float b0, float b1, float b2,
                                        int i0, int i1, int i2, int lane,
                                        int sel[3], float seld[3]) {
    int j = 0;
    #pragma unroll
    for (int s = 0; s < 3; s++) {
        float cv = (j == 0) ? b0 : ((j == 1) ? b1 : ((j == 2) ? b2 : 3.4e38f));
        int   ci = (j == 0) ? i0 : ((j == 1) ? i1 : i2);
        float rv = cv; int rl = lane;
        #pragma unroll
        for (int off = 16; off; off >>= 1) {
            float ov = __shfl_down_sync(0xffffffffu, rv, off);
            int   ol = __shfl_down_sync(0xffffffffu, rl, off);
            if (ov < rv) { rv = ov; rl = ol; }
        }
        int wl = __shfl_sync(0xffffffffu, rl, 0);
        seld[s] = __shfl_sync(0xffffffffu, rv, 0);
        sel[s]  = __shfl_sync(0xffffffffu, ci, wl);
        if (lane == wl) j++;
    }
}

// ---------------- fused KNN(3) + h1 build + stages 2-4 ----------------
// smem (floats): h1s[0,9216) h2s[9216,13824); overlays in h2s region pre-stage2:
//   c4 (float4[512]) [9216,11264), w1qs [11264,12288), c1s [12288,12544)
//   h3s overlays h1s after stage2. total 13824 floats = 55296 B -> 4 CTAs/SM
__global__ void __launch_bounds__(256, 4) knnreg_kernel(
        const float* __restrict__ qpts,
        const float* __restrict__ rb2, const float* __restrict__ rb3,
        const float* __restrict__ r4, const float* __restrict__ rb4,
        float* __restrict__ out) {
    extern __shared__ float sm[];
    float*  h1s  = sm;
    float*  h2s  = sm + 9216;
    float*  h3s  = sm;
    float4* c4   = (float4*)(sm + 9216);
    float*  w1qs = sm + 11264;
    float*  c1s  = sm + 12288;
    int t = threadIdx.x;
    int bb = blockIdx.x >> 9, tile = blockIdx.x & 511;
    int qbase = tile * 32;
    int warp = t >> 5, lane = t & 31;

    for (int i = t; i < 1024; i += 256) w1qs[i] = g_w1q[i];
    if (t < 256) c1s[t] = g_c1[bb * 256 + t];

    int q0 = qbase + warp * 4;
    float qx[4], qy[4], qz[4];
    #pragma unroll
    for (int r = 0; r < 4; r++) {
        qx[r] = qpts[bb * 3 * NQ + q0 + r];
        qy[r] = qpts[bb * 3 * NQ + NQ + q0 + r];
        qz[r] = qpts[bb * 3 * NQ + 2 * NQ + q0 + r];
    }

    float bd[4][3];
    int   bi[4][3];
    #pragma unroll
    for (int r = 0; r < 4; r++)
        #pragma unroll
        for (int s = 0; s < 3; s++) { bd[r][s] = 3.4e38f; bi[r][s] = 0; }

    const float4* pbase = g_pts4 + bb * NPTS;
    for (int ch = 0; ch < NPTS / CHUNK; ch++) {
        __syncthreads();
        for (int i = t; i < CHUNK; i += 256) c4[i] = pbase[ch * CHUNK + i];
        __syncthreads();
        int gb = ch * CHUNK;
        for (int p = lane; p < CHUNK; p += 32) {
            float4 P = c4[p];
            #pragma unroll
            for (int r = 0; r < 4; r++) {
                float dd = fmaf(qx[r], P.x, fmaf(qy[r], P.y, fmaf(qz[r], P.z, P.w)));
                if (dd < bd[r][2]) {
                    if (dd < bd[r][1]) {
                        bd[r][2] = bd[r][1]; bi[r][2] = bi[r][1];
                        if (dd < bd[r][0]) { bd[r][1] = bd[r][0]; bi[r][1] = bi[r][0]; bd[r][0] = dd; bi[r][0] = gb + p; }
                        else               { bd[r][1] = dd; bi[r][1] = gb + p; }
                    } else { bd[r][2] = dd; bi[r][2] = gb + p; }
                }
            }
        }
    }
    __syncthreads();

    // ---- per query: weights + gather G rows -> h1 ----
    #pragma unroll
    for (int r = 0; r < 4; r++) {
        int sel[3]; float seld[3];
        merge3d(bd[r][0], bd[r][1], bd[r][2], bi[r][0], bi[r][1], bi[r][2], lane, sel, seld);
        int ql = warp * 4 + r;

        float q2r = fmaf(qx[r], qx[r], fmaf(qy[r], qy[r], qz[r] * qz[r]));
        float wk0 = 1.f / (sqrtf(fmaxf(seld[0] + q2r, 0.f)) + 1e-8f);
        float wk1 = 1.f / (sqrtf(fmaxf(seld[1] + q2r, 0.f)) + 1e-8f);
        float wk2 = 1.f / (sqrtf(fmaxf(seld[2] + q2r, 0.f)) + 1e-8f);
        float inv = 1.f / (wk0 + wk1 + wk2);
        wk0 *= inv; wk1 *= inv; wk2 *= inv;

        const float4* G0 = (const float4*)(g_G + (size_t)(bb * NPTS + sel[0]) * 256);
        const float4* G1 = (const float4*)(g_G + (size_t)(bb * NPTS + sel[1]) * 256);
        const float4* G2 = (const float4*)(g_G + (size_t)(bb * NPTS + sel[2]) * 256);
        const float4* WQ = (const float4*)w1qs;
        #pragma unroll
        for (int h = 0; h < 2; h++) {
            int f4 = lane * 2 + h;
            float4 a = G0[f4], b = G1[f4], c = G2[f4];
            #pragma unroll
            for (int e = 0; e < 4; e++) {
                int oc = f4 * 4 + e;
                float4 w = WQ[oc];
                float ga  = e == 0 ? a.x : e == 1 ? a.y : e == 2 ? a.z : a.w;
                float gb2 = e == 0 ? b.x : e == 1 ? b.y : e == 2 ? b.z : b.w;
                float gc  = e == 0 ? c.x : e == 1 ? c.y : e == 2 ? c.z : c.w;
                float v = c1s[oc];
                v = fmaf(qx[r], w.x, v);
                v = fmaf(qy[r], w.y, v);
                v = fmaf(qz[r], w.z, v);
                v = fmaf(wk0, ga, v);
                v = fmaf(wk1, gb2, v);
                v = fmaf(wk2, gc, v);
                h1s[oc * LDQ + ql] = fmaxf(v, 0.f);
            }
        }
    }
    __syncthreads();

    int ocb = t & 63;
    int q2 = (t >> 6) * 8;

    // ---- stage 2: 256 -> 128 ----
    {
        ULL acc[2][4];
        #pragma unroll
        for (int j = 0; j < 2; j++) {
            ULL c = pk2(rb2[ocb + 64 * j]);
            #pragma unroll
            for (int i = 0; i < 4; i++) acc[j][i] = c;
        }
        const float4* wb = (const float4*)g_r2o;
        float4 w0 = wb[ocb], w1 = wb[ocb + 64];
        for (int kg = 0; kg < 64; kg++) {
            int kn = (kg < 63) ? kg + 1 : kg;
            float4 n0 = wb[kn * 128 + ocb];
            float4 n1 = wb[kn * 128 + ocb + 64];
            #pragma unroll
            for (int kk = 0; kk < 4; kk++) {
                const float* arow = h1s + (kg * 4 + kk) * LDQ + q2;
                ulonglong2 aA = *(const ulonglong2*)(arow);
                ulonglong2 aB = *(const ulonglong2*)(arow + 4);
                float s0 = kk == 0 ? w0.x : kk == 1 ? w0.y : kk == 2 ? w0.z : w0.w;
                float s1 = kk == 0 ? w1.x : kk == 1 ? w1.y : kk == 2 ? w1.z : w1.w;
                ULL v0 = pk2(s0), v1 = pk2(s1);
                fma2(acc[0][0], v0, aA.x); fma2(acc[0][1], v0, aA.y);
                fma2(acc[0][2], v0, aB.x); fma2(acc[0][3], v0, aB.y);
                fma2(acc[1][0], v1, aA.x); fma2(acc[1][1], v1, aA.y);
                fma2(acc[1][2], v1, aB.x); fma2(acc[1][3], v1, aB.y);
            }
            w0 = n0; w1 = n1;
        }
        __syncthreads();
        #pragma unroll
        for (int j = 0; j < 2; j++) {
            float* hrow = h2s + (ocb + 64 * j) * LDQ + q2;
            #pragma unroll
            for (int i = 0; i < 4; i++) {
                float lo, hi; upk2(acc[j][i], lo, hi);
                hrow[2 * i]     = fmaxf(lo, 0.f);
                hrow[2 * i + 1] = fmaxf(hi, 0.f);
            }
        }
    }
    __syncthreads();

    // ---- stage 3: 128 -> 64 ----
    {
        ULL acc[4];
        ULL c = pk2(rb3[ocb]);
        #pragma unroll
        for (int i = 0; i < 4; i++) acc[i] = c;
        const float4* wb = (const float4*)g_r3o;
        for (int kg = 0; kg < 32; kg++) {
            float4 w = wb[kg * 64 + ocb];
            #pragma unroll
            for (int kk = 0; kk < 4; kk++) {
                const float* arow = h2s + (kg * 4 + kk) * LDQ + q2;
                ulonglong2 aA = *(const ulonglong2*)(arow);
                ulonglong2 aB = *(const ulonglong2*)(arow + 4);
                float ws = kk == 0 ? w.x : kk == 1 ? w.y : kk == 2 ? w.z : w.w;
                ULL wv = pk2(ws);
                fma2(acc[0], wv, aA.x);
                fma2(acc[1], wv, aA.y);
                fma2(acc[2], wv, aB.x);
                fma2(acc[3], wv, aB.y);
            }
        }
        __syncthreads();
        float* hrow = h3s + ocb * LDQ + q2;
        #pragma unroll
        for (int i = 0; i < 4; i++) {
            float lo, hi; upk2(acc[i], lo, hi);
            hrow[2 * i]     = fmaxf(lo, 0.f);
            hrow[2 * i + 1] = fmaxf(hi, 0.f);
        }
    }
    __syncthreads();

    // ---- stage 4: 64 -> 1 ----
    {
        int w4 = t >> 5, l4 = t & 31;
        int qloc = w4 * 4 + (l4 >> 3);
        int c0 = l4 & 7;
        float p = 0.f;
        #pragma unroll
        for (int jj = 0; jj < 8; jj++) {
            int c = c0 + jj * 8;
            p = fmaf(r4[c], h3s[c * LDQ + qloc], p);
        }
        p += __shfl_xor_sync(0xffffffffu, p, 1);
        p += __shfl_xor_sync(0xffffffffu, p, 2);
        p += __shfl_xor_sync(0xffffffffu, p, 4);
        if ((l4 & 7) == 0) out[bb * NQ + qbase + qloc] = p + rb4[0];
    }
}

// ---------------- launch ----------------
extern "C" void kernel_launch(void* const* d_in, const int* in_sizes, int n_in,
                              void* d_out, int out_size) {
    const float* opts = (const float*)d_in[0];
    const float* qpts = (const float*)d_in[1];
    const float* w1 = (const float*)d_in[2];
    const float* b1 = (const float*)d_in[3];
    const float* w2 = (const float*)d_in[4];
    const float* b2 = (const float*)d_in[5];
    const float* w3 = (const float*)d_in[6];
    const float* b3 = (const float*)d_in[7];
    const float* r1 = (const float*)d_in[8];
    const float* rb1 = (const float*)d_in[9];
    const float* r2 = (const float*)d_in[10];
    const float* rb2 = (const float*)d_in[11];
    const float* r3 = (const float*)d_in[12];
    const float* rb3 = (const float*)d_in[13];
    const float* r4 = (const float*)d_in[14];
    const float* rb4 = (const float*)d_in[15];
    float* out = (float*)d_out;

    cudaFuncSetAttribute(feat_kernel, cudaFuncAttributeMaxDynamicSharedMemorySize, 191104);
    cudaFuncSetAttribute(gfeat_kernel, cudaFuncAttributeMaxDynamicSharedMemorySize, 64512);
    cudaFuncSetAttribute(knnreg_kernel, cudaFuncAttributeMaxDynamicSharedMemorySize, 55296);

    prep_kernel<<<64, 256>>>(opts, r1, r2, r3);
    feat_kernel<<<BATCH * (NPTS / 32), 256, 191104>>>(opts, w1, b1, w2, b2, w3, b3);
    c1_kernel<<<BATCH * 8, 256>>>(r1, rb1);
    gfeat_kernel<<<BATCH * 128, 256, 64512>>>();
    knnreg_kernel<<<BATCH * (NQ / 32), 256, 55296>>>(qpts, rb2, rb3, r4, rb4, out);
}